// round 15
// baseline (speedup 1.0000x reference)
#include <cuda_runtime.h>
#include <math.h>

#define Bq 4
#define Nn 500
#define Dd 2048
#define Kk 50
#define H0 28
#define C0c 512
#define NP0 (H0*H0)
#define H1 14
#define C1c 1024
#define NP1 (H1*H1)
#define IMG 224
#define KS 33
#define RAD 16

#define NU 200            // padded unique-row work list length (<= Bq*Kk)
#define UPW0 20
#define NCH0 (NU/UPW0)    // 10 chunks -> 784*10 = 7840 warps
#define UPW1 10
#define NCH1 (NU/UPW1)    // 20 chunks -> 196*20 = 3920 warps
#define BLK0 ((NP0*NCH0)/8)   // 980
#define BLK1 ((NP1*NCH1)/8)   // 490

#define DIST_BLKS ((Nn*32 + 255)/256)      // 63 (one warp per bank row)

#define RPB 2                  // tail rows per block
#define TAIL_BLKS (Bq*IMG/RPB) // 448

// ---------------- device scratch ----------------
__device__ float    g_d2[Bq*Nn];
__device__ unsigned g_mask[Nn];      // batch bitmask per bank row
__device__ unsigned g_list[256];     // compacted (mask<<16)|n, padded w/ 0
__device__ int      g_done2;         // select completion count (reset by tail)
__device__ int      g_ucount;        // list length             (reset by tail)
__device__ unsigned g_min0[Bq*NP0];  // min DISTANCE (sqrt'ed), float bits
__device__ unsigned g_min1[Bq*NP1];
__device__ float    g_C0[IMG*H0];    // composite blur*resize operator (y-major)
__device__ float    g_C1[IMG*H1];
__device__ float    g_C0T[H0*IMG];   // transposed for coalesced hpass
__device__ float    g_C1T[H1*IMG];

__device__ __forceinline__ int reflect(int i) {
    if (i < 0) return -i;
    if (i > IMG - 1) return 2*(IMG - 1) - i;
    return i;
}

// ---------------- distances (one warp per bank row, all 4 batches)
//                  + operator precompute + distributed init ----------------
__global__ void dist_kernel(const float* __restrict__ x2,
                            const float* __restrict__ f2) {
    int tid = threadIdx.x;
    if (blockIdx.x >= DIST_BLKS) {
        // ----- operator precompute: C = Blur(33,reflect101) * BilinearUp(H->224) -----
        int lvl = blockIdx.x - DIST_BLKS;          // 0 or 1
        int H = lvl ? H1 : H0;
        float* Cm  = lvl ? g_C1  : g_C0;
        float* CmT = lvl ? g_C1T : g_C0T;
        int y = tid;
        if (y >= IMG) return;
        float w[KS];
        float wsum = 0.f;
        #pragma unroll
        for (int o = 0; o < KS; o++) {
            float xx = (float)o - (float)RAD;
            w[o] = expf(-(xx*xx) / (2.0f * 4.0f * 4.0f));
            wsum += w[o];
        }
        __shared__ float sC[IMG * H0];
        float* row = sC + y * H;
        for (int i = 0; i < H; i++) row[i] = 0.f;
        float scale = (float)H / (float)IMG;
        #pragma unroll
        for (int o = 0; o < KS; o++) {
            int t = reflect(y + o - RAD);
            float fy = ((float)t + 0.5f) * scale - 0.5f;
            float f0 = floorf(fy);
            float wf = fy - f0;
            int i0 = (int)f0;
            int i0c = max(i0, 0), i1c = min(i0 + 1, H - 1);
            float ww = w[o] / wsum;
            row[i0c] += ww * (1.f - wf);
            row[i1c] += ww * wf;
        }
        for (int i = 0; i < H; i++) {
            Cm[y * H + i]    = row[i];
            CmT[i * IMG + y] = row[i];
        }
        return;
    }
    {   // distributed init: g_mask, g_min0, g_min1
        int z = blockIdx.x * 256 + tid;
        if (z < Nn) g_mask[z] = 0u;
        if (z < Bq*NP0) g_min0[z] = 0x7F800000u;
        if (z < Bq*NP1) g_min1[z] = 0x7F800000u;
    }
    int gw = (blockIdx.x * blockDim.x + tid) >> 5;
    int lane = tid & 31;
    if (gw >= Nn) return;
    int n = gw;
    const float4* f = (const float4*)(f2 + (size_t)n * Dd);
    float acc[Bq];
    #pragma unroll
    for (int bb = 0; bb < Bq; bb++) acc[bb] = 0.f;
    #pragma unroll
    for (int j = 0; j < 16; j++) {                 // 16*32*4 = 2048 floats
        float4 c = __ldcs(&f[lane + j*32]);        // streaming: touch-once
        #pragma unroll
        for (int bb = 0; bb < Bq; bb++) {
            float4 a = ((const float4*)(x2 + (size_t)bb * Dd))[lane + j*32];
            float dx = a.x - c.x, dy = a.y - c.y, dz = a.z - c.z, dw = a.w - c.w;
            acc[bb] += dx*dx + dy*dy + dz*dz + dw*dw;
        }
    }
    #pragma unroll
    for (int bb = 0; bb < Bq; bb++) {
        float s = acc[bb];
        #pragma unroll
        for (int o = 16; o; o >>= 1) s += __shfl_xor_sync(0xFFFFFFFFu, s, o);
        if (lane == 0) g_d2[bb*Nn + n] = s;
    }
}

// ---------------- select top-K + score + mask; LAST block compacts work list ----------------
__global__ void select_kernel(float* __restrict__ out_score) {
    int b = blockIdx.x;
    int tid = threadIdx.x;
    __shared__ float sd[Nn];
    __shared__ float ssel[Kk];
    __shared__ int sdone2;
    for (int n = tid; n < Nn; n += 256) sd[n] = g_d2[b*Nn + n];
    __syncthreads();
    for (int n = tid; n < Nn; n += 256) {
        float dn = sd[n];
        int r = 0;
        for (int m = 0; m < Nn; m++) {
            float dm = sd[m];
            r += (dm < dn) || (dm == dn && m < n);
        }
        if (r < Kk) {
            ssel[r] = sqrtf(fmaxf(dn, 0.f));
            atomicOr(&g_mask[n], 1u << b);
        }
    }
    __syncthreads();
    if (tid == 0) {
        float s = 0.f;
        for (int i = 0; i < Kk; i++) s += ssel[i];
        out_score[b] = s / (float)Kk;
    }
    __threadfence();
    if (tid == 0) sdone2 = atomicAdd(&g_done2, 1);
    __syncthreads();
    if (sdone2 == Bq - 1) {
        __threadfence();
        for (int n = tid; n < Nn; n += 256) {
            unsigned m = atomicOr(&g_mask[n], 0u);   // atomic read
            if (m) {
                int p = atomicAdd(&g_ucount, 1);
                g_list[p] = (m << 16) | (unsigned)n;
            }
        }
    }
}

// ---------------- level 0 minmap: x held in registers across 20 entries ----------------
__device__ __forceinline__ void minmap_body0(const float* __restrict__ x,
                                             const float* __restrict__ f,
                                             int wid, int lane) {
    int chunk = wid % NCH0;
    int pix   = wid / NCH0;

    float4 xr[Bq][4];                       // 64 regs: all 4 batches' x row
    #pragma unroll
    for (int bb = 0; bb < Bq; bb++) {
        const float4* xv = (const float4*)(x + ((size_t)(bb*NP0 + pix))*C0c);
        #pragma unroll
        for (int r = 0; r < 4; r++) xr[bb][r] = xv[lane + r*32];
    }

    float mn[Bq];
    #pragma unroll
    for (int bb = 0; bb < Bq; bb++) mn[bb] = 3.4e38f;
    unsigned seen = 0u;

    #pragma unroll
    for (int uu = 0; uu < UPW0; uu++) {
        unsigned e = g_list[chunk + uu*NCH0];
        unsigned msk = e >> 16;
        if (!msk) continue;                 // warp-uniform
        int n = e & 0xFFFFu;
        seen |= msk;

        const float4* fv = (const float4*)(f + ((size_t)n*NP0 + pix)*C0c);
        float4 v[4];
        #pragma unroll
        for (int r = 0; r < 4; r++) v[r] = __ldcs(&fv[lane + r*32]);

        float acc[Bq];
        #pragma unroll
        for (int bb = 0; bb < Bq; bb++) acc[bb] = 0.f;
        #pragma unroll
        for (int bb = 0; bb < Bq; bb++) {
            if (!((msk >> bb) & 1u)) continue;
            #pragma unroll
            for (int r = 0; r < 4; r++) {
                float dx = v[r].x - xr[bb][r].x, dy = v[r].y - xr[bb][r].y;
                float dz = v[r].z - xr[bb][r].z, dw = v[r].w - xr[bb][r].w;
                acc[bb] += dx*dx + dy*dy + dz*dz + dw*dw;
            }
        }
        #pragma unroll
        for (int bb = 0; bb < Bq; bb++) {
            if (!((msk >> bb) & 1u)) continue;
            float s = acc[bb];
            #pragma unroll
            for (int o = 16; o; o >>= 1) s += __shfl_xor_sync(0xFFFFFFFFu, s, o);
            mn[bb] = fminf(mn[bb], s);
        }
    }
    if (lane == 0) {
        #pragma unroll
        for (int bb = 0; bb < Bq; bb++)
            if ((seen >> bb) & 1u)
                atomicMin(g_min0 + bb*NP0 + pix, __float_as_uint(sqrtf(mn[bb])));
    }
}

// ---------------- level 1 minmap: entry loop of 10, x L1-resident ----------------
__device__ __forceinline__ void minmap_body1(const float* __restrict__ x,
                                             const float* __restrict__ f,
                                             int wid, int lane) {
    int chunk = wid % NCH1;
    int pix   = wid / NCH1;

    const float4* xbase[Bq];
    #pragma unroll
    for (int bb = 0; bb < Bq; bb++)
        xbase[bb] = (const float4*)(x + ((size_t)(bb*NP1 + pix))*C1c);

    float mn[Bq];
    #pragma unroll
    for (int bb = 0; bb < Bq; bb++) mn[bb] = 3.4e38f;
    unsigned seen = 0u;

    #pragma unroll
    for (int uu = 0; uu < UPW1; uu++) {
        unsigned e = g_list[chunk + uu*NCH1];
        unsigned msk = e >> 16;
        if (!msk) continue;                 // warp-uniform
        int n = e & 0xFFFFu;
        seen |= msk;

        float acc[Bq];
        #pragma unroll
        for (int bb = 0; bb < Bq; bb++) acc[bb] = 0.f;

        #pragma unroll
        for (int cc = 0; cc < 2; cc++) {    // C1c/512
            const float4* fv = (const float4*)(f + ((size_t)n*NP1 + pix)*C1c + cc*512);
            float4 v[4];
            #pragma unroll
            for (int r = 0; r < 4; r++) v[r] = __ldcs(&fv[lane + r*32]);
            #pragma unroll
            for (int bb = 0; bb < Bq; bb++) {
                if (!((msk >> bb) & 1u)) continue;
                const float4* xv = xbase[bb] + cc*128;
                #pragma unroll
                for (int r = 0; r < 4; r++) {
                    float4 a = xv[lane + r*32];
                    float dx = v[r].x - a.x, dy = v[r].y - a.y;
                    float dz = v[r].z - a.z, dw = v[r].w - a.w;
                    acc[bb] += dx*dx + dy*dy + dz*dz + dw*dw;
                }
            }
        }
        #pragma unroll
        for (int bb = 0; bb < Bq; bb++) {
            if (!((msk >> bb) & 1u)) continue;
            float s = acc[bb];
            #pragma unroll
            for (int o = 16; o; o >>= 1) s += __shfl_xor_sync(0xFFFFFFFFu, s, o);
            mn[bb] = fminf(mn[bb], s);
        }
    }
    if (lane == 0) {
        #pragma unroll
        for (int bb = 0; bb < Bq; bb++)
            if ((seen >> bb) & 1u)
                atomicMin(g_min1 + bb*NP1 + pix, __float_as_uint(sqrtf(mn[bb])));
    }
}

__global__ void __launch_bounds__(256) minmap_fused(
        const float* __restrict__ x0, const float* __restrict__ f0,
        const float* __restrict__ x1, const float* __restrict__ f1) {
    int lane = threadIdx.x & 31;
    int wIn  = threadIdx.x >> 5;
    if (blockIdx.x < BLK0) {
        minmap_body0(x0, f0, blockIdx.x * 8 + wIn, lane);
    } else {
        minmap_body1(x1, f1, (blockIdx.x - BLK0) * 8 + wIn, lane);
    }
}

// ---------------- fused tail: 2 rows/block, smem staged ----------------
__global__ void tail_kernel(float* __restrict__ out_mask) {
    int b     = blockIdx.x / (IMG / RPB);
    int ybase = (blockIdx.x % (IMG / RPB)) * RPB;
    int x = threadIdx.x;             // 0..223

    __shared__ float sm0[NP0];
    __shared__ float sm1[NP1];
    __shared__ float T0[RPB][H0];
    __shared__ float T1[RPB][H1];

    const unsigned* m0 = g_min0 + b * NP0;
    const unsigned* m1 = g_min1 + b * NP1;
    for (int i = x; i < NP0; i += IMG) sm0[i] = __uint_as_float(m0[i]);
    if (x < NP1) sm1[x] = __uint_as_float(m1[x]);
    __syncthreads();

    // vertical contraction: 56 threads for level0, 28 for level1
    if (x < RPB * H0) {
        int y = x / H0, i = x % H0;
        const float* Crow = g_C0 + (ybase + y) * H0;
        float s = 0.f;
        #pragma unroll
        for (int t = 0; t < H0; t++) s += Crow[t] * sm0[t*H0 + i];
        T0[y][i] = s;
    } else if (x >= 64 && x < 64 + RPB * H1) {
        int z = x - 64;
        int y = z / H1, j = z % H1;
        const float* Crow = g_C1 + (ybase + y) * H1;
        float s = 0.f;
        #pragma unroll
        for (int t = 0; t < H1; t++) s += Crow[t] * sm1[t*H1 + j];
        T1[y][j] = s;
    }
    __syncthreads();

    // horizontal contraction + average — coalesced via transposed operator
    #pragma unroll
    for (int y = 0; y < RPB; y++) {
        float s0 = 0.f, s1 = 0.f;
        #pragma unroll
        for (int i = 0; i < H0; i++) s0 += g_C0T[i*IMG + x] * T0[y][i];
        #pragma unroll
        for (int j = 0; j < H1; j++) s1 += g_C1T[j*IMG + x] * T1[y][j];
        out_mask[(b*IMG + ybase + y) * IMG + x] = 0.5f * (s0 + s1);
    }

    // reset pipeline state for the next graph replay (runs last)
    if (blockIdx.x == 0) {
        if (x < 224) g_list[x] = 0u;
        if (x < 32) g_list[224 + x] = 0u;
        if (x == 0) { g_done2 = 0; g_ucount = 0; }
    }
}

// ---------------- launch ----------------
extern "C" void kernel_launch(void* const* d_in, const int* in_sizes, int n_in,
                              void* d_out, int out_size) {
    const float* x0 = (const float*)d_in[0];
    const float* x1 = (const float*)d_in[1];
    const float* x2 = (const float*)d_in[2];
    const float* f0 = (const float*)d_in[3];
    const float* f1 = (const float*)d_in[4];
    const float* f2 = (const float*)d_in[5];
    float* out = (float*)d_out;           // [0..3] = score, [4..] = mask

    dist_kernel<<<DIST_BLKS + 2, 256>>>(x2, f2);
    select_kernel<<<Bq, 256>>>(out);
    minmap_fused<<<BLK0 + BLK1, 256>>>(x0, f0, x1, f1);
    tail_kernel<<<TAIL_BLKS, IMG>>>(out + 4);
}

// round 16
// speedup vs baseline: 1.5776x; 1.5776x over previous
#include <cuda_runtime.h>
#include <math.h>

#define Bq 4
#define Nn 500
#define Dd 2048
#define Kk 50
#define H0 28
#define C0c 512
#define NP0 (H0*H0)
#define H1 14
#define C1c 1024
#define NP1 (H1*H1)
#define IMG 224
#define KS 33
#define RAD 16

#define NU 200            // padded unique-row work list length (<= Bq*Kk)
#define UPW0 5
#define NCH0 (NU/UPW0)    // 40 chunks -> 784*40 = 31360 warps
#define UPW1 2
#define NCH1 (NU/UPW1)    // 100 chunks -> 196*100 = 19600 warps
#define BLK0 ((NP0*NCH0)/8)   // 3920
#define BLK1 ((NP1*NCH1)/8)   // 2450

#define DIST_BLKS ((Nn*32 + 255)/256)      // 63 (one warp per bank row)

#define RPB 4                  // tail rows per block
#define TAIL_BLKS (Bq*IMG/RPB) // 224

// ---------------- device scratch ----------------
__device__ float    g_d2[Bq*Nn];
__device__ unsigned g_mask[Nn];      // batch bitmask per bank row
__device__ unsigned g_list[256];     // compacted (mask<<16)|n, padded w/ 0
__device__ int      g_done2;         // select completion count (reset by tail)
__device__ int      g_ucount;        // list length             (reset by tail)
__device__ unsigned g_min0[Bq*NP0];  // min DISTANCE (sqrt'ed), float bits
__device__ unsigned g_min1[Bq*NP1];
__device__ float    g_C0[IMG*H0];    // composite blur*resize operator (y-major)
__device__ float    g_C1[IMG*H1];
__device__ float    g_C0T[H0*IMG];   // transposed for coalesced hpass
__device__ float    g_C1T[H1*IMG];

__device__ __forceinline__ int reflect(int i) {
    if (i < 0) return -i;
    if (i > IMG - 1) return 2*(IMG - 1) - i;
    return i;
}

// ---------------- distances (one warp per bank row, all 4 batches)
//                  + operator precompute + distributed init ----------------
__global__ void dist_kernel(const float* __restrict__ x2,
                            const float* __restrict__ f2) {
    int tid = threadIdx.x;
    if (blockIdx.x >= DIST_BLKS) {
        // ----- operator precompute: C = Blur(33,reflect101) * BilinearUp(H->224) -----
        int lvl = blockIdx.x - DIST_BLKS;          // 0 or 1
        int H = lvl ? H1 : H0;
        float* Cm  = lvl ? g_C1  : g_C0;
        float* CmT = lvl ? g_C1T : g_C0T;
        int y = tid;
        if (y >= IMG) return;
        float w[KS];
        float wsum = 0.f;
        #pragma unroll
        for (int o = 0; o < KS; o++) {
            float xx = (float)o - (float)RAD;
            w[o] = expf(-(xx*xx) / (2.0f * 4.0f * 4.0f));
            wsum += w[o];
        }
        __shared__ float sC[IMG * H0];
        float* row = sC + y * H;
        for (int i = 0; i < H; i++) row[i] = 0.f;
        float scale = (float)H / (float)IMG;
        #pragma unroll
        for (int o = 0; o < KS; o++) {
            int t = reflect(y + o - RAD);
            float fy = ((float)t + 0.5f) * scale - 0.5f;
            float f0 = floorf(fy);
            float wf = fy - f0;
            int i0 = (int)f0;
            int i0c = max(i0, 0), i1c = min(i0 + 1, H - 1);
            float ww = w[o] / wsum;
            row[i0c] += ww * (1.f - wf);
            row[i1c] += ww * wf;
        }
        for (int i = 0; i < H; i++) {
            Cm[y * H + i]    = row[i];
            CmT[i * IMG + y] = row[i];
        }
        return;
    }
    {   // distributed init: g_mask, g_min0, g_min1
        int z = blockIdx.x * 256 + tid;
        if (z < Nn) g_mask[z] = 0u;
        if (z < Bq*NP0) g_min0[z] = 0x7F800000u;
        if (z < Bq*NP1) g_min1[z] = 0x7F800000u;
    }
    int gw = (blockIdx.x * blockDim.x + tid) >> 5;
    int lane = tid & 31;
    if (gw >= Nn) return;
    int n = gw;
    const float4* f = (const float4*)(f2 + (size_t)n * Dd);
    float acc[Bq];
    #pragma unroll
    for (int bb = 0; bb < Bq; bb++) acc[bb] = 0.f;
    #pragma unroll
    for (int j = 0; j < 16; j++) {                 // 16*32*4 = 2048 floats
        float4 c = __ldcs(&f[lane + j*32]);        // streaming: touch-once
        #pragma unroll
        for (int bb = 0; bb < Bq; bb++) {
            float4 a = ((const float4*)(x2 + (size_t)bb * Dd))[lane + j*32];
            float dx = a.x - c.x, dy = a.y - c.y, dz = a.z - c.z, dw = a.w - c.w;
            acc[bb] += dx*dx + dy*dy + dz*dz + dw*dw;
        }
    }
    #pragma unroll
    for (int bb = 0; bb < Bq; bb++) {
        float s = acc[bb];
        #pragma unroll
        for (int o = 16; o; o >>= 1) s += __shfl_xor_sync(0xFFFFFFFFu, s, o);
        if (lane == 0) g_d2[bb*Nn + n] = s;
    }
}

// ---------------- select top-K + score + mask; LAST block compacts work list ----------------
__global__ void select_kernel(float* __restrict__ out_score) {
    int b = blockIdx.x;
    int tid = threadIdx.x;
    __shared__ float sd[Nn];
    __shared__ float ssel[Kk];
    __shared__ int sdone2;
    for (int n = tid; n < Nn; n += 256) sd[n] = g_d2[b*Nn + n];
    __syncthreads();
    for (int n = tid; n < Nn; n += 256) {
        float dn = sd[n];
        int r = 0;
        for (int m = 0; m < Nn; m++) {
            float dm = sd[m];
            r += (dm < dn) || (dm == dn && m < n);
        }
        if (r < Kk) {
            ssel[r] = sqrtf(fmaxf(dn, 0.f));
            atomicOr(&g_mask[n], 1u << b);
        }
    }
    __syncthreads();
    if (tid == 0) {
        float s = 0.f;
        for (int i = 0; i < Kk; i++) s += ssel[i];
        out_score[b] = s / (float)Kk;
    }
    __threadfence();
    if (tid == 0) sdone2 = atomicAdd(&g_done2, 1);
    __syncthreads();
    if (sdone2 == Bq - 1) {
        __threadfence();
        for (int n = tid; n < Nn; n += 256) {
            unsigned m = atomicOr(&g_mask[n], 0u);   // atomic read
            if (m) {
                int p = atomicAdd(&g_ucount, 1);
                g_list[p] = (m << 16) | (unsigned)n;
            }
        }
    }
}

// ---------------- min-distance maps: balanced unique-row work list ----------------
// f rows touch-once -> __ldcs streaming; x rows default-cached (L1/L2-hot).
// ~51K warps, <=5 entries/warp: measured optimum for latency hiding.
template<int C, int NP, int UPW, int NCH>
__device__ __forceinline__ void minmap_body(const float* __restrict__ x,
                                            const float* __restrict__ f,
                                            unsigned* __restrict__ gmin,
                                            int wid, int lane) {
    int chunk = wid % NCH;
    int pix   = wid / NCH;

    const float4* xbase[Bq];
    #pragma unroll
    for (int bb = 0; bb < Bq; bb++)
        xbase[bb] = (const float4*)(x + ((size_t)(bb*NP + pix))*C);

    float mn[Bq];
    #pragma unroll
    for (int bb = 0; bb < Bq; bb++) mn[bb] = 3.4e38f;
    unsigned seen = 0u;

    #pragma unroll
    for (int uu = 0; uu < UPW; uu++) {
        unsigned e = g_list[chunk + uu*NCH];       // strided
        unsigned msk = e >> 16;
        if (!msk) continue;                        // warp-uniform
        int n = e & 0xFFFFu;
        seen |= msk;

        float acc[Bq];
        #pragma unroll
        for (int bb = 0; bb < Bq; bb++) acc[bb] = 0.f;

        constexpr int NCC = C / 512;
        #pragma unroll
        for (int cc = 0; cc < NCC; cc++) {
            const float4* fv = (const float4*)(f + ((size_t)n*NP + pix)*C + cc*512);
            float4 v[4];
            #pragma unroll
            for (int r = 0; r < 4; r++) v[r] = __ldcs(&fv[lane + r*32]);  // streaming
            #pragma unroll
            for (int bb = 0; bb < Bq; bb++) {
                if (!((msk >> bb) & 1u)) continue; // warp-uniform
                const float4* xv = xbase[bb] + cc*128;
                #pragma unroll
                for (int r = 0; r < 4; r++) {
                    float4 a = xv[lane + r*32];
                    float dx = v[r].x - a.x, dy = v[r].y - a.y;
                    float dz = v[r].z - a.z, dw = v[r].w - a.w;
                    acc[bb] += dx*dx + dy*dy + dz*dz + dw*dw;
                }
            }
        }
        #pragma unroll
        for (int bb = 0; bb < Bq; bb++) {
            if (!((msk >> bb) & 1u)) continue;
            float s = acc[bb];
            #pragma unroll
            for (int o = 16; o; o >>= 1) s += __shfl_xor_sync(0xFFFFFFFFu, s, o);
            mn[bb] = fminf(mn[bb], s);
        }
    }
    if (lane == 0) {
        #pragma unroll
        for (int bb = 0; bb < Bq; bb++)
            if ((seen >> bb) & 1u)
                atomicMin(gmin + bb*NP + pix, __float_as_uint(sqrtf(mn[bb])));
    }
}

__global__ void minmap_fused(const float* __restrict__ x0, const float* __restrict__ f0,
                             const float* __restrict__ x1, const float* __restrict__ f1) {
    int lane = threadIdx.x & 31;
    int wIn  = threadIdx.x >> 5;
    if (blockIdx.x < BLK0) {
        int wid = blockIdx.x * 8 + wIn;
        minmap_body<C0c, NP0, UPW0, NCH0>(x0, f0, g_min0, wid, lane);
    } else {
        int wid = (blockIdx.x - BLK0) * 8 + wIn;
        minmap_body<C1c, NP1, UPW1, NCH1>(x1, f1, g_min1, wid, lane);
    }
}

// ---------------- fused tail: 4 rows/block (grid 224 >= SMs), smem staged ----------------
__global__ void tail_kernel(float* __restrict__ out_mask) {
    int b     = blockIdx.x / (IMG / RPB);
    int ybase = (blockIdx.x % (IMG / RPB)) * RPB;
    int x = threadIdx.x;             // 0..223

    __shared__ float sm0[NP0];
    __shared__ float sm1[NP1];
    __shared__ float T0[RPB][H0];
    __shared__ float T1[RPB][H1];

    const unsigned* m0 = g_min0 + b * NP0;
    const unsigned* m1 = g_min1 + b * NP1;
    for (int i = x; i < NP0; i += IMG) sm0[i] = __uint_as_float(m0[i]);
    if (x < NP1) sm1[x] = __uint_as_float(m1[x]);
    __syncthreads();

    // vertical contraction: 112 threads for level0, 56 for level1
    if (x < RPB * H0) {
        int y = x / H0, i = x % H0;
        const float* Crow = g_C0 + (ybase + y) * H0;
        float s = 0.f;
        #pragma unroll
        for (int t = 0; t < H0; t++) s += Crow[t] * sm0[t*H0 + i];
        T0[y][i] = s;
    } else if (x >= 128 && x < 128 + RPB * H1) {
        int z = x - 128;
        int y = z / H1, j = z % H1;
        const float* Crow = g_C1 + (ybase + y) * H1;
        float s = 0.f;
        #pragma unroll
        for (int t = 0; t < H1; t++) s += Crow[t] * sm1[t*H1 + j];
        T1[y][j] = s;
    }
    __syncthreads();

    // horizontal contraction + average — coalesced via transposed operator;
    // operator loads amortized over RPB rows
    #pragma unroll
    for (int y = 0; y < RPB; y++) {
        float s0 = 0.f, s1 = 0.f;
        #pragma unroll
        for (int i = 0; i < H0; i++) s0 += g_C0T[i*IMG + x] * T0[y][i];
        #pragma unroll
        for (int j = 0; j < H1; j++) s1 += g_C1T[j*IMG + x] * T1[y][j];
        out_mask[(b*IMG + ybase + y) * IMG + x] = 0.5f * (s0 + s1);
    }

    // reset pipeline state for the next graph replay (runs last)
    if (blockIdx.x == 0) {
        if (x < 224) g_list[x] = 0u;
        if (x < 32) g_list[224 + x] = 0u;
        if (x == 0) { g_done2 = 0; g_ucount = 0; }
    }
}

// ---------------- launch ----------------
extern "C" void kernel_launch(void* const* d_in, const int* in_sizes, int n_in,
                              void* d_out, int out_size) {
    const float* x0 = (const float*)d_in[0];
    const float* x1 = (const float*)d_in[1];
    const float* x2 = (const float*)d_in[2];
    const float* f0 = (const float*)d_in[3];
    const float* f1 = (const float*)d_in[4];
    const float* f2 = (const float*)d_in[5];
    float* out = (float*)d_out;           // [0..3] = score, [4..] = mask

    dist_kernel<<<DIST_BLKS + 2, 256>>>(x2, f2);
    select_kernel<<<Bq, 256>>>(out);
    minmap_fused<<<BLK0 + BLK1, 256>>>(x0, f0, x1, f1);
    tail_kernel<<<TAIL_BLKS, IMG>>>(out + 4);
}